// round 7
// baseline (speedup 1.0000x reference)
#include <cuda_runtime.h>
#include <cuda_fp16.h>
#include <math.h>
#include <stdint.h>

// ---------------------------------------------------------------------------
// TT feed-forward via dense weight materialization + fp16 mma.sync GEMMs
// (fp32 accumulate), ks-pipelined fragments, fused aux kernels.
//   W1t[4096,1024], W2t[1024,4096] (transposed, fp16)
//   Xh = half(x);  H = half(GELU(Xh @ W1t^T + b1));  out = H @ W2t^T + b2
// ---------------------------------------------------------------------------

__device__ float  g_P  [2][128 * 256 * 16];
__device__ __half g_W1t[4096 * 1024];
__device__ __half g_W2t[1024 * 4096];
__device__ __half g_H  [4096 * 4096];
__device__ __half g_Xh [4096 * 1024];

// ------------------------------ helpers -----------------------------------
__device__ __forceinline__ uint32_t smem_u32(const void* p) {
    uint32_t a;
    asm("{ .reg .u64 t; cvta.to.shared.u64 t, %1; cvt.u32.u64 %0, t; }"
        : "=r"(a) : "l"(p));
    return a;
}
__device__ __forceinline__ void cp16(uint32_t dst, const void* src) {
    asm volatile("cp.async.cg.shared.global [%0], [%1], 16;"
                 :: "r"(dst), "l"(src));
}
#define CP_COMMIT() asm volatile("cp.async.commit_group;")
#define CP_WAIT(n)  asm volatile("cp.async.wait_group %0;" :: "n"(n))

__device__ __forceinline__ void mma_f16(float c[4], const uint32_t a[4],
                                        const uint32_t b[2]) {
    asm volatile(
        "mma.sync.aligned.m16n8k16.row.col.f32.f16.f16.f32 "
        "{%0,%1,%2,%3}, {%4,%5,%6,%7}, {%8,%9}, {%0,%1,%2,%3};"
        : "+f"(c[0]), "+f"(c[1]), "+f"(c[2]), "+f"(c[3])
        : "r"(a[0]), "r"(a[1]), "r"(a[2]), "r"(a[3]), "r"(b[0]), "r"(b[1]));
}
__device__ __forceinline__ void ldsm4(uint32_t& r0, uint32_t& r1,
                                      uint32_t& r2, uint32_t& r3,
                                      uint32_t addr) {
    asm volatile("ldmatrix.sync.aligned.m8n8.x4.shared.b16 {%0,%1,%2,%3}, [%4];"
                 : "=r"(r0), "=r"(r1), "=r"(r2), "=r"(r3) : "r"(addr));
}
__device__ __forceinline__ uint32_t pack2(float a, float b) {
    __half2 h = __floats2half2_rn(a, b);
    return *(uint32_t*)&h;
}

// ------------------------- weight materialization -------------------------
// Both pair contractions in one kernel. half = bid>>9 selects fc1/fc2.
__global__ void pair_both_kernel(const float* __restrict__ c10,
                                 const float* __restrict__ c11,
                                 const float* __restrict__ c20,
                                 const float* __restrict__ c21) {
    int bid  = blockIdx.x;
    int half = bid >> 9;
    int idx  = (bid & 511) * 256 + threadIdx.x;   // 131072 per half
    const float* c0 = half ? c20 : c10;
    const float* c1 = half ? c21 : c11;
    int r2q  = idx & 3;
    int j    = (idx >> 2) & 255;
    int pair = idx >> 10;
    const float* c0p = c0 + pair * 16;
    float4 acc = make_float4(0, 0, 0, 0);
#pragma unroll
    for (int r1 = 0; r1 < 16; ++r1) {
        float w = c0p[r1];
        float4 v = ((const float4*)(c1 + (r1 * 256 + j) * 16))[r2q];
        acc.x += w * v.x; acc.y += w * v.y;
        acc.z += w * v.z; acc.w += w * v.w;
    }
    ((float4*)g_P[half])[idx] = acc;
}

// Both W materializations in one kernel (blocks 0..2047 -> W1t, else W2t).
__global__ void weights_kernel(const float* __restrict__ c12,
                               const float* __restrict__ c22) {
    __shared__ float s[2048];
    int bid = blockIdx.x;
    if (bid < 2048) {
        // ---- W1t[m, n]: m hidden (16,16,16), n embed (8,16,8) ----
        for (int i = threadIdx.x; i < 2048; i += blockDim.x) {
            int r2 = i >> 7, n3 = (i >> 4) & 7, m3 = i & 15;   // c12:[r2][n3][m3]
            s[(r2 * 16 + m3) * 8 + n3] = c12[i];
        }
        __syncthreads();
        int idx = bid * 256 + threadIdx.x;    // 524288
        int nq = idx & 127;
        int m  = idx >> 7;
        int n1 = nq >> 4, n2 = nq & 15;
        int m1 = m >> 8, m2 = (m >> 4) & 15, m3 = m & 15;
        const float4* p4 = (const float4*)(g_P[0] +
            (((n1 * 16 + m1) * 256) + (n2 * 16 + m2)) * 16);
        float pv[16];
        *(float4*)&pv[0]  = p4[0]; *(float4*)&pv[4]  = p4[1];
        *(float4*)&pv[8]  = p4[2]; *(float4*)&pv[12] = p4[3];
        float acc[8] = {0, 0, 0, 0, 0, 0, 0, 0};
#pragma unroll
        for (int r2 = 0; r2 < 16; ++r2) {
            const float* sr = s + (r2 * 16 + m3) * 8;
#pragma unroll
            for (int j = 0; j < 8; ++j) acc[j] += pv[r2] * sr[j];
        }
        uint4 o;
        o.x = pack2(acc[0], acc[1]); o.y = pack2(acc[2], acc[3]);
        o.z = pack2(acc[4], acc[5]); o.w = pack2(acc[6], acc[7]);
        *(uint4*)(g_W1t + (size_t)m * 1024 + nq * 8) = o;
    } else {
        // ---- W2t[m, n]: m embed (8,16,8), n hidden (16,16,16) ----
        for (int i = threadIdx.x; i < 2048; i += blockDim.x) {
            int r2 = i >> 7, n3 = (i >> 3) & 15, m3 = i & 7;   // c22:[r2][n3][m3]
            s[(r2 * 8 + m3) * 16 + n3] = c22[i];
        }
        __syncthreads();
        int idx = (bid - 2048) * 256 + threadIdx.x;   // 524288
        int nh = idx & 511;
        int m  = idx >> 9;
        int n1 = nh >> 5, n2 = (nh >> 1) & 15, n3b = (nh & 1) * 8;
        int m1 = m >> 7, m2 = (m >> 3) & 15, m3 = m & 7;
        const float4* p4 = (const float4*)(g_P[1] +
            (((n1 * 8 + m1) * 256) + (n2 * 16 + m2)) * 16);
        float pv[16];
        *(float4*)&pv[0]  = p4[0]; *(float4*)&pv[4]  = p4[1];
        *(float4*)&pv[8]  = p4[2]; *(float4*)&pv[12] = p4[3];
        float acc[8] = {0, 0, 0, 0, 0, 0, 0, 0};
#pragma unroll
        for (int r2 = 0; r2 < 16; ++r2) {
            const float* sr = s + (r2 * 8 + m3) * 16 + n3b;
#pragma unroll
            for (int j = 0; j < 8; ++j) acc[j] += pv[r2] * sr[j];
        }
        uint4 o;
        o.x = pack2(acc[0], acc[1]); o.y = pack2(acc[2], acc[3]);
        o.z = pack2(acc[4], acc[5]); o.w = pack2(acc[6], acc[7]);
        *(uint4*)(g_W2t + (size_t)m * 4096 + nh * 8) = o;
    }
}

__global__ void xhalf_kernel(const float4* __restrict__ x, uint4* __restrict__ o) {
    int i = blockIdx.x * blockDim.x + threadIdx.x;      // 524288
    float4 v0 = x[2 * i], v1 = x[2 * i + 1];
    uint4 r;
    r.x = pack2(v0.x, v0.y); r.y = pack2(v0.z, v0.w);
    r.z = pack2(v1.x, v1.y); r.w = pack2(v1.z, v1.w);
    o[i] = r;
}

// ------------------------------- fp16 GEMM --------------------------------
// C[M,N] = A[M,K] * B[N,K]^T + bias.  fuse=1: C(half) = GELU(.), else C float.
// CTA 128x128, BK=64 halves, 8 warps (64x32), 3-stage cp.async,
// ks-pipelined (double-buffered) ldmatrix fragments.
#define STAGE_B 32768

__global__ void __launch_bounds__(256, 2) gemm_f16(
    const __half* __restrict__ A, const __half* __restrict__ B,
    const float* __restrict__ bias, void* __restrict__ Cv,
    int K, int N, int fuse) {
    extern __shared__ char smem[];
    uint32_t sb = smem_u32(smem);

    int tid  = threadIdx.x;
    int lane = tid & 31;
    int q    = lane & 3;
    int g8   = lane >> 2;
    int warp = tid >> 5;
    int wm   = (warp & 1) * 64;
    int wn   = (warp >> 1) * 32;

    size_t rowBase = (size_t)blockIdx.y * 128;
    size_t colBase = (size_t)blockIdx.x * 128;
    const __half* Ag = A + rowBase * (size_t)K;
    const __half* Bg = B + colBase * (size_t)K;

#define LOAD_STAGE(s, buf) do {                                              \
    uint32_t stg_ = sb + (uint32_t)(buf) * STAGE_B;                          \
    size_t koff = (size_t)(s) * 64;                                          \
    _Pragma("unroll")                                                        \
    for (int i = 0; i < 4; ++i) {                                            \
        int id = tid + 256 * i;                                              \
        int r = id >> 3, j = id & 7;                                         \
        uint32_t off = (uint32_t)(r * 128 + ((j ^ (r & 7)) << 4));           \
        cp16(stg_ + off,         Ag + (size_t)r * K + koff + j * 8);         \
        cp16(stg_ + 16384 + off, Bg + (size_t)r * K + koff + j * 8);         \
    }                                                                        \
    CP_COMMIT();                                                             \
} while (0)

    // ldmatrix geometry: 16x16 b16 tile; row-in-tile = lane&15, half = lane>>4.
    // swizzle term (row & 7) == (lane & 7) for every tile (bases are 8-row
    // aligned), so it is warp-uniform-per-lane: one scalar.
    int rT  = lane & 15;
    int cT  = lane >> 4;
    int swz = lane & 7;
    uint32_t aB0 = (uint32_t)((wm + rT) * 128);            // + mt*2048
    uint32_t bB0 = (uint32_t)(16384 + (wn + rT) * 128);    // + p*2048

    // load fragment set for k16-step `ks` from stage base `stg`
#define LD_FRAGS(fa, fb, stg, ks) do {                                       \
    uint32_t xo = ((((uint32_t)((ks) * 2) + (uint32_t)cT) ^ (uint32_t)swz) << 4); \
    _Pragma("unroll")                                                        \
    for (int mt = 0; mt < 4; ++mt)                                           \
        ldsm4((fa)[mt][0], (fa)[mt][1], (fa)[mt][2], (fa)[mt][3],            \
              (stg) + aB0 + (uint32_t)(mt * 2048) + xo);                     \
    _Pragma("unroll")                                                        \
    for (int p = 0; p < 2; ++p) {                                            \
        uint32_t r0, r1, r2, r3;                                             \
        ldsm4(r0, r1, r2, r3, (stg) + bB0 + (uint32_t)(p * 2048) + xo);      \
        (fb)[2 * p][0] = r0;     (fb)[2 * p][1] = r2;                        \
        (fb)[2 * p + 1][0] = r1; (fb)[2 * p + 1][1] = r3;                    \
    }                                                                        \
} while (0)

    float acc[4][4][4];
#pragma unroll
    for (int i = 0; i < 4; ++i)
#pragma unroll
        for (int j = 0; j < 4; ++j)
#pragma unroll
            for (int k = 0; k < 4; ++k) acc[i][j][k] = 0.f;

    uint32_t af[2][4][4], bf[2][4][2];

    int nS = K >> 6;
    LOAD_STAGE(0, 0);
    LOAD_STAGE(1, 1);

    int buf = 0;
    for (int s = 0; s < nS; ++s) {
        if (s + 2 < nS) CP_WAIT(1); else CP_WAIT(0);
        __syncthreads();
        if (s + 2 < nS) {
            int nb = buf - 1; if (nb < 0) nb += 3;
            LOAD_STAGE(s + 2, nb);
        }

        uint32_t stg = sb + (uint32_t)buf * STAGE_B;
        LD_FRAGS(af[0], bf[0], stg, 0);
#pragma unroll
        for (int ks = 0; ks < 4; ++ks) {
            int cur = ks & 1;
            if (ks < 3) LD_FRAGS(af[cur ^ 1], bf[cur ^ 1], stg, ks + 1);
#pragma unroll
            for (int mt = 0; mt < 4; ++mt)
#pragma unroll
                for (int nt = 0; nt < 4; ++nt)
                    mma_f16(acc[mt][nt], af[cur][mt], bf[cur][nt]);
        }
        buf = (buf == 2) ? 0 : buf + 1;
    }

    // ---- epilogue ----
#pragma unroll
    for (int nt = 0; nt < 4; ++nt) {
        int col = (int)colBase + wn + nt * 8 + 2 * q;
        float bx = bias[col], by = bias[col + 1];
#pragma unroll
        for (int mt = 0; mt < 4; ++mt) {
            size_t row0 = rowBase + wm + mt * 16 + g8;
            float v0 = acc[mt][nt][0] + bx;
            float v1 = acc[mt][nt][1] + by;
            float v2 = acc[mt][nt][2] + bx;
            float v3 = acc[mt][nt][3] + by;
            if (fuse) {
                v0 = 0.5f * v0 * (1.0f + erff(v0 * 0.70710678118654752f));
                v1 = 0.5f * v1 * (1.0f + erff(v1 * 0.70710678118654752f));
                v2 = 0.5f * v2 * (1.0f + erff(v2 * 0.70710678118654752f));
                v3 = 0.5f * v3 * (1.0f + erff(v3 * 0.70710678118654752f));
                __half* C = (__half*)Cv;
                *(uint32_t*)&C[row0 * (size_t)N + col]       = pack2(v0, v1);
                *(uint32_t*)&C[(row0 + 8) * (size_t)N + col] = pack2(v2, v3);
            } else {
                float* C = (float*)Cv;
                *(float2*)&C[row0 * (size_t)N + col]       = make_float2(v0, v1);
                *(float2*)&C[(row0 + 8) * (size_t)N + col] = make_float2(v2, v3);
            }
        }
    }
#undef LOAD_STAGE
#undef LD_FRAGS
}

// --------------------------------- launch ---------------------------------
extern "C" void kernel_launch(void* const* d_in, const int* in_sizes, int n_in,
                              void* d_out, int out_size) {
    const float* x   = (const float*)d_in[0];
    const float* c10 = (const float*)d_in[1];
    const float* c11 = (const float*)d_in[2];
    const float* c12 = (const float*)d_in[3];
    const float* b1  = (const float*)d_in[4];
    const float* c20 = (const float*)d_in[5];
    const float* c21 = (const float*)d_in[6];
    const float* c22 = (const float*)d_in[7];
    const float* b2  = (const float*)d_in[8];
    float* out = (float*)d_out;

    __half *pW1t, *pW2t, *pH, *pXh;
    cudaGetSymbolAddress((void**)&pW1t, g_W1t);
    cudaGetSymbolAddress((void**)&pW2t, g_W2t);
    cudaGetSymbolAddress((void**)&pH,   g_H);
    cudaGetSymbolAddress((void**)&pXh,  g_Xh);

    const int SMEM = 3 * STAGE_B;   // 98304
    cudaFuncSetAttribute(gemm_f16, cudaFuncAttributeMaxDynamicSharedMemorySize,
                         SMEM);

    pair_both_kernel<<<1024, 256>>>(c10, c11, c20, c21);
    weights_kernel<<<4096, 256>>>(c12, c22);
    xhalf_kernel<<<2048, 256>>>((const float4*)x, (uint4*)pXh);

    // GEMM1: H = half(GELU(Xh @ W1t^T + b1))   grid 32x32
    gemm_f16<<<dim3(32, 32), 256, SMEM>>>(pXh, pW1t, b1, pH, 1024, 4096, 1);
    // GEMM2: out = H @ W2t^T + b2              grid 8x32
    gemm_f16<<<dim3(8, 32), 256, SMEM>>>(pH, pW2t, b2, out, 4096, 1024, 0);
}

// round 8
// speedup vs baseline: 1.0250x; 1.0250x over previous
#include <cuda_runtime.h>
#include <cuda_fp16.h>
#include <math.h>
#include <stdint.h>

// ---------------------------------------------------------------------------
// TT feed-forward via dense weight materialization + fp16 mma.sync GEMMs
// (fp32 accumulate). CTA 128x128, warp 64x32, BK=64 halves, 3-stage cp.async,
// SW128 swizzle, ldmatrix.x4 fragments (compiler-scheduled), hoisted addresses.
//   W1t[4096,1024], W2t[1024,4096] (transposed, fp16)
//   Xh = half(x);  H = half(GELU(Xh @ W1t^T + b1));  out = H @ W2t^T + b2
// ---------------------------------------------------------------------------

__device__ float  g_P  [2][128 * 256 * 16];
__device__ __half g_W1t[4096 * 1024];
__device__ __half g_W2t[1024 * 4096];
__device__ __half g_H  [4096 * 4096];
__device__ __half g_Xh [4096 * 1024];

// ------------------------------ helpers -----------------------------------
__device__ __forceinline__ uint32_t smem_u32(const void* p) {
    uint32_t a;
    asm("{ .reg .u64 t; cvta.to.shared.u64 t, %1; cvt.u32.u64 %0, t; }"
        : "=r"(a) : "l"(p));
    return a;
}
__device__ __forceinline__ void cp16(uint32_t dst, const void* src) {
    asm volatile("cp.async.cg.shared.global [%0], [%1], 16;"
                 :: "r"(dst), "l"(src));
}
#define CP_COMMIT() asm volatile("cp.async.commit_group;")
#define CP_WAIT(n)  asm volatile("cp.async.wait_group %0;" :: "n"(n))

__device__ __forceinline__ void mma_f16(float c[4], const uint32_t a[4],
                                        const uint32_t b[2]) {
    asm volatile(
        "mma.sync.aligned.m16n8k16.row.col.f32.f16.f16.f32 "
        "{%0,%1,%2,%3}, {%4,%5,%6,%7}, {%8,%9}, {%0,%1,%2,%3};"
        : "+f"(c[0]), "+f"(c[1]), "+f"(c[2]), "+f"(c[3])
        : "r"(a[0]), "r"(a[1]), "r"(a[2]), "r"(a[3]), "r"(b[0]), "r"(b[1]));
}
__device__ __forceinline__ void ldsm4(uint32_t& r0, uint32_t& r1,
                                      uint32_t& r2, uint32_t& r3,
                                      uint32_t addr) {
    asm volatile("ldmatrix.sync.aligned.m8n8.x4.shared.b16 {%0,%1,%2,%3}, [%4];"
                 : "=r"(r0), "=r"(r1), "=r"(r2), "=r"(r3) : "r"(addr));
}
__device__ __forceinline__ uint32_t pack2(float a, float b) {
    __half2 h = __floats2half2_rn(a, b);
    return *(uint32_t*)&h;
}

// ------------------------- weight materialization -------------------------
__global__ void pair_both_kernel(const float* __restrict__ c10,
                                 const float* __restrict__ c11,
                                 const float* __restrict__ c20,
                                 const float* __restrict__ c21) {
    int bid  = blockIdx.x;
    int half = bid >> 9;
    int idx  = (bid & 511) * 256 + threadIdx.x;   // 131072 per half
    const float* c0 = half ? c20 : c10;
    const float* c1 = half ? c21 : c11;
    int r2q  = idx & 3;
    int j    = (idx >> 2) & 255;
    int pair = idx >> 10;
    const float* c0p = c0 + pair * 16;
    float4 acc = make_float4(0, 0, 0, 0);
#pragma unroll
    for (int r1 = 0; r1 < 16; ++r1) {
        float w = c0p[r1];
        float4 v = ((const float4*)(c1 + (r1 * 256 + j) * 16))[r2q];
        acc.x += w * v.x; acc.y += w * v.y;
        acc.z += w * v.z; acc.w += w * v.w;
    }
    ((float4*)g_P[half])[idx] = acc;
}

__global__ void weights_kernel(const float* __restrict__ c12,
                               const float* __restrict__ c22) {
    __shared__ float s[2048];
    int bid = blockIdx.x;
    if (bid < 2048) {
        // ---- W1t[m, n]: m hidden (16,16,16), n embed (8,16,8) ----
        for (int i = threadIdx.x; i < 2048; i += blockDim.x) {
            int r2 = i >> 7, n3 = (i >> 4) & 7, m3 = i & 15;   // c12:[r2][n3][m3]
            s[(r2 * 16 + m3) * 8 + n3] = c12[i];
        }
        __syncthreads();
        int idx = bid * 256 + threadIdx.x;    // 524288
        int nq = idx & 127;
        int m  = idx >> 7;
        int n1 = nq >> 4, n2 = nq & 15;
        int m1 = m >> 8, m2 = (m >> 4) & 15, m3 = m & 15;
        const float4* p4 = (const float4*)(g_P[0] +
            (((n1 * 16 + m1) * 256) + (n2 * 16 + m2)) * 16);
        float pv[16];
        *(float4*)&pv[0]  = p4[0]; *(float4*)&pv[4]  = p4[1];
        *(float4*)&pv[8]  = p4[2]; *(float4*)&pv[12] = p4[3];
        float acc[8] = {0, 0, 0, 0, 0, 0, 0, 0};
#pragma unroll
        for (int r2 = 0; r2 < 16; ++r2) {
            const float* sr = s + (r2 * 16 + m3) * 8;
#pragma unroll
            for (int j = 0; j < 8; ++j) acc[j] += pv[r2] * sr[j];
        }
        uint4 o;
        o.x = pack2(acc[0], acc[1]); o.y = pack2(acc[2], acc[3]);
        o.z = pack2(acc[4], acc[5]); o.w = pack2(acc[6], acc[7]);
        *(uint4*)(g_W1t + (size_t)m * 1024 + nq * 8) = o;
    } else {
        // ---- W2t[m, n]: m embed (8,16,8), n hidden (16,16,16) ----
        for (int i = threadIdx.x; i < 2048; i += blockDim.x) {
            int r2 = i >> 7, n3 = (i >> 3) & 15, m3 = i & 7;   // c22:[r2][n3][m3]
            s[(r2 * 8 + m3) * 16 + n3] = c22[i];
        }
        __syncthreads();
        int idx = (bid - 2048) * 256 + threadIdx.x;   // 524288
        int nh = idx & 511;
        int m  = idx >> 9;
        int n1 = nh >> 5, n2 = (nh >> 1) & 15, n3b = (nh & 1) * 8;
        int m1 = m >> 7, m2 = (m >> 3) & 15, m3 = m & 7;
        const float4* p4 = (const float4*)(g_P[1] +
            (((n1 * 8 + m1) * 256) + (n2 * 16 + m2)) * 16);
        float pv[16];
        *(float4*)&pv[0]  = p4[0]; *(float4*)&pv[4]  = p4[1];
        *(float4*)&pv[8]  = p4[2]; *(float4*)&pv[12] = p4[3];
        float acc[8] = {0, 0, 0, 0, 0, 0, 0, 0};
#pragma unroll
        for (int r2 = 0; r2 < 16; ++r2) {
            const float* sr = s + (r2 * 8 + m3) * 16 + n3b;
#pragma unroll
            for (int j = 0; j < 8; ++j) acc[j] += pv[r2] * sr[j];
        }
        uint4 o;
        o.x = pack2(acc[0], acc[1]); o.y = pack2(acc[2], acc[3]);
        o.z = pack2(acc[4], acc[5]); o.w = pack2(acc[6], acc[7]);
        *(uint4*)(g_W2t + (size_t)m * 4096 + nh * 8) = o;
    }
}

__global__ void xhalf_kernel(const float4* __restrict__ x, uint4* __restrict__ o) {
    int i = blockIdx.x * blockDim.x + threadIdx.x;      // 524288
    float4 v0 = x[2 * i], v1 = x[2 * i + 1];
    uint4 r;
    r.x = pack2(v0.x, v0.y); r.y = pack2(v0.z, v0.w);
    r.z = pack2(v1.x, v1.y); r.w = pack2(v1.z, v1.w);
    o[i] = r;
}

// ------------------------------- fp16 GEMM --------------------------------
// C[M,N] = A[M,K] * B[N,K]^T + bias.  FUSE=1: C(half)=GELU(.), else C float.
#define STAGE_B 32768

template <int FUSE>
__global__ void __launch_bounds__(256, 2) gemm_f16(
    const __half* __restrict__ A, const __half* __restrict__ B,
    const float* __restrict__ bias, void* __restrict__ Cv,
    int K, int N) {
    extern __shared__ char smem[];
    uint32_t sb = smem_u32(smem);

    int tid  = threadIdx.x;
    int lane = tid & 31;
    int q    = lane & 3;
    int g8   = lane >> 2;
    int warp = tid >> 5;
    int wm   = (warp & 1) * 64;
    int wn   = (warp >> 1) * 32;

    size_t rowBase = (size_t)blockIdx.y * 128;
    size_t colBase = (size_t)blockIdx.x * 128;

    // ---- hoisted cp.async geometry: r = tid>>3 + 32*i, j = tid&7 ----------
    int r0 = tid >> 3, j0 = tid & 7;
    uint32_t stOff = (uint32_t)(r0 * 128 + ((j0 ^ (r0 & 7)) << 4)); // +4096*i
    const __half* Asrc = A + (rowBase + r0) * (size_t)K + j0 * 8;   // advances
    const __half* Bsrc = B + (colBase + r0) * (size_t)K + j0 * 8;
    size_t strideA = (size_t)32 * K;   // row step between chunks

#define LOAD_STAGE(buf) do {                                                 \
    uint32_t stg_ = sb + (uint32_t)(buf) * STAGE_B;                          \
    _Pragma("unroll")                                                        \
    for (int i = 0; i < 4; ++i) {                                            \
        cp16(stg_ + stOff + (uint32_t)(i * 4096),         Asrc + i * strideA); \
        cp16(stg_ + 16384 + stOff + (uint32_t)(i * 4096), Bsrc + i * strideA); \
    }                                                                        \
    CP_COMMIT();                                                             \
    Asrc += 64; Bsrc += 64;                                                  \
} while (0)

    // ---- ldmatrix geometry: swizzle term (row&7)==(lane&7) tile-invariant -
    int rT  = lane & 15;
    int cT  = lane >> 4;
    int swz = lane & 7;
    uint32_t aB0 = (uint32_t)((wm + rT) * 128);            // + mt*2048
    uint32_t bB0 = (uint32_t)(16384 + (wn + rT) * 128);    // + p*2048
    uint32_t xo[4];
#pragma unroll
    for (int ks = 0; ks < 4; ++ks)
        xo[ks] = ((((uint32_t)(ks * 2) + (uint32_t)cT) ^ (uint32_t)swz) << 4);

    float acc[4][4][4];
#pragma unroll
    for (int i = 0; i < 4; ++i)
#pragma unroll
        for (int j = 0; j < 4; ++j)
#pragma unroll
            for (int k = 0; k < 4; ++k) acc[i][j][k] = 0.f;

    int nS = K >> 6;
    LOAD_STAGE(0);
    LOAD_STAGE(1);

    int buf = 0;
    for (int s = 0; s < nS; ++s) {
        if (s + 2 < nS) CP_WAIT(1); else CP_WAIT(0);
        __syncthreads();
        if (s + 2 < nS) {
            int nb = buf - 1; if (nb < 0) nb += 3;    // (s+2)%3
            LOAD_STAGE(nb);
        }

        uint32_t stg = sb + (uint32_t)buf * STAGE_B;
#pragma unroll
        for (int ks = 0; ks < 4; ++ks) {
            uint32_t af[4][4], bf[4][2];
#pragma unroll
            for (int mt = 0; mt < 4; ++mt)
                ldsm4(af[mt][0], af[mt][1], af[mt][2], af[mt][3],
                      stg + aB0 + (uint32_t)(mt * 2048) + xo[ks]);
#pragma unroll
            for (int p = 0; p < 2; ++p) {
                uint32_t t0, t1, t2, t3;
                ldsm4(t0, t1, t2, t3, stg + bB0 + (uint32_t)(p * 2048) + xo[ks]);
                bf[2 * p][0] = t0;     bf[2 * p][1] = t2;
                bf[2 * p + 1][0] = t1; bf[2 * p + 1][1] = t3;
            }
#pragma unroll
            for (int mt = 0; mt < 4; ++mt)
#pragma unroll
                for (int nt = 0; nt < 4; ++nt)
                    mma_f16(acc[mt][nt], af[mt], bf[nt]);
        }
        buf = (buf == 2) ? 0 : buf + 1;
    }

    // ---- epilogue ----
#pragma unroll
    for (int nt = 0; nt < 4; ++nt) {
        int col = (int)colBase + wn + nt * 8 + 2 * q;
        float bx = bias[col], by = bias[col + 1];
#pragma unroll
        for (int mt = 0; mt < 4; ++mt) {
            size_t row0 = rowBase + wm + mt * 16 + g8;
            float v0 = acc[mt][nt][0] + bx;
            float v1 = acc[mt][nt][1] + by;
            float v2 = acc[mt][nt][2] + bx;
            float v3 = acc[mt][nt][3] + by;
            if (FUSE) {
                v0 = 0.5f * v0 * (1.0f + erff(v0 * 0.70710678118654752f));
                v1 = 0.5f * v1 * (1.0f + erff(v1 * 0.70710678118654752f));
                v2 = 0.5f * v2 * (1.0f + erff(v2 * 0.70710678118654752f));
                v3 = 0.5f * v3 * (1.0f + erff(v3 * 0.70710678118654752f));
                __half* C = (__half*)Cv;
                *(uint32_t*)&C[row0 * (size_t)N + col]       = pack2(v0, v1);
                *(uint32_t*)&C[(row0 + 8) * (size_t)N + col] = pack2(v2, v3);
            } else {
                float* C = (float*)Cv;
                *(float2*)&C[row0 * (size_t)N + col]       = make_float2(v0, v1);
                *(float2*)&C[(row0 + 8) * (size_t)N + col] = make_float2(v2, v3);
            }
        }
    }
#undef LOAD_STAGE
}

// --------------------------------- launch ---------------------------------
extern "C" void kernel_launch(void* const* d_in, const int* in_sizes, int n_in,
                              void* d_out, int out_size) {
    const float* x   = (const float*)d_in[0];
    const float* c10 = (const float*)d_in[1];
    const float* c11 = (const float*)d_in[2];
    const float* c12 = (const float*)d_in[3];
    const float* b1  = (const float*)d_in[4];
    const float* c20 = (const float*)d_in[5];
    const float* c21 = (const float*)d_in[6];
    const float* c22 = (const float*)d_in[7];
    const float* b2  = (const float*)d_in[8];
    float* out = (float*)d_out;

    __half *pW1t, *pW2t, *pH, *pXh;
    cudaGetSymbolAddress((void**)&pW1t, g_W1t);
    cudaGetSymbolAddress((void**)&pW2t, g_W2t);
    cudaGetSymbolAddress((void**)&pH,   g_H);
    cudaGetSymbolAddress((void**)&pXh,  g_Xh);

    const int SMEM = 3 * STAGE_B;   // 98304
    cudaFuncSetAttribute(gemm_f16<1>, cudaFuncAttributeMaxDynamicSharedMemorySize,
                         SMEM);
    cudaFuncSetAttribute(gemm_f16<0>, cudaFuncAttributeMaxDynamicSharedMemorySize,
                         SMEM);

    pair_both_kernel<<<1024, 256>>>(c10, c11, c20, c21);
    weights_kernel<<<4096, 256>>>(c12, c22);
    xhalf_kernel<<<2048, 256>>>((const float4*)x, (uint4*)pXh);

    // GEMM1: H = half(GELU(Xh @ W1t^T + b1))   grid 32x32
    gemm_f16<1><<<dim3(32, 32), 256, SMEM>>>(pXh, pW1t, b1, pH, 1024, 4096);
    // GEMM2: out = H @ W2t^T + b2              grid 8x32
    gemm_f16<0><<<dim3(8, 32), 256, SMEM>>>(pH, pW2t, b2, out, 4096, 1024);
}

// round 9
// speedup vs baseline: 1.0391x; 1.0137x over previous
#include <cuda_runtime.h>
#include <cuda_fp16.h>
#include <math.h>
#include <stdint.h>

// ---------------------------------------------------------------------------
// TT feed-forward via dense weight materialization + fp16 mma.sync GEMMs
// (fp32 accumulate). CTA 128x128, 512 threads, warp tile 32x32 (low regs ->
// occ 2 = 32 warps/SM), BK=64 halves, 3-stage cp.async, SW128 swizzle.
//   W1t[4096,1024], W2t[1024,4096] (transposed, fp16)
//   Xh = half(x);  H = half(GELU(Xh @ W1t^T + b1));  out = H @ W2t^T + b2
// ---------------------------------------------------------------------------

__device__ float  g_P  [2][128 * 256 * 16];
__device__ __half g_W1t[4096 * 1024];
__device__ __half g_W2t[1024 * 4096];
__device__ __half g_H  [4096 * 4096];
__device__ __half g_Xh [4096 * 1024];

// ------------------------------ helpers -----------------------------------
__device__ __forceinline__ uint32_t smem_u32(const void* p) {
    uint32_t a;
    asm("{ .reg .u64 t; cvta.to.shared.u64 t, %1; cvt.u32.u64 %0, t; }"
        : "=r"(a) : "l"(p));
    return a;
}
__device__ __forceinline__ void cp16(uint32_t dst, const void* src) {
    asm volatile("cp.async.cg.shared.global [%0], [%1], 16;"
                 :: "r"(dst), "l"(src));
}
#define CP_COMMIT() asm volatile("cp.async.commit_group;")
#define CP_WAIT(n)  asm volatile("cp.async.wait_group %0;" :: "n"(n))

__device__ __forceinline__ void mma_f16(float c[4], const uint32_t a[4],
                                        const uint32_t b[2]) {
    asm volatile(
        "mma.sync.aligned.m16n8k16.row.col.f32.f16.f16.f32 "
        "{%0,%1,%2,%3}, {%4,%5,%6,%7}, {%8,%9}, {%0,%1,%2,%3};"
        : "+f"(c[0]), "+f"(c[1]), "+f"(c[2]), "+f"(c[3])
        : "r"(a[0]), "r"(a[1]), "r"(a[2]), "r"(a[3]), "r"(b[0]), "r"(b[1]));
}
__device__ __forceinline__ void ldsm4(uint32_t& r0, uint32_t& r1,
                                      uint32_t& r2, uint32_t& r3,
                                      uint32_t addr) {
    asm volatile("ldmatrix.sync.aligned.m8n8.x4.shared.b16 {%0,%1,%2,%3}, [%4];"
                 : "=r"(r0), "=r"(r1), "=r"(r2), "=r"(r3) : "r"(addr));
}
__device__ __forceinline__ uint32_t pack2(float a, float b) {
    __half2 h = __floats2half2_rn(a, b);
    return *(uint32_t*)&h;
}

// ----------------------- prep: xhalf + both pair contractions --------------
// blocks [0,2048): x -> half.  blocks [2048,3072): pair contraction.
__global__ void prep_kernel(const float* __restrict__ x, uint4* __restrict__ xh,
                            const float* __restrict__ c10,
                            const float* __restrict__ c11,
                            const float* __restrict__ c20,
                            const float* __restrict__ c21) {
    int bid = blockIdx.x;
    if (bid < 2048) {
        int i = bid * 256 + threadIdx.x;      // 524288
        const float4* xv = (const float4*)x;
        float4 v0 = xv[2 * i], v1 = xv[2 * i + 1];
        uint4 r;
        r.x = pack2(v0.x, v0.y); r.y = pack2(v0.z, v0.w);
        r.z = pack2(v1.x, v1.y); r.w = pack2(v1.z, v1.w);
        xh[i] = r;
    } else {
        int b = bid - 2048;
        int half = b >> 9;
        int idx  = (b & 511) * 256 + threadIdx.x;   // 131072 per half
        const float* c0 = half ? c20 : c10;
        const float* c1 = half ? c21 : c11;
        int r2q  = idx & 3;
        int j    = (idx >> 2) & 255;
        int pair = idx >> 10;
        const float* c0p = c0 + pair * 16;
        float4 acc = make_float4(0, 0, 0, 0);
#pragma unroll
        for (int r1 = 0; r1 < 16; ++r1) {
            float w = c0p[r1];
            float4 v = ((const float4*)(c1 + (r1 * 256 + j) * 16))[r2q];
            acc.x += w * v.x; acc.y += w * v.y;
            acc.z += w * v.z; acc.w += w * v.w;
        }
        ((float4*)g_P[half])[idx] = acc;
    }
}

// ------------------------- weight materialization -------------------------
__global__ void weights_kernel(const float* __restrict__ c12,
                               const float* __restrict__ c22) {
    __shared__ float s[2048];
    int bid = blockIdx.x;
    if (bid < 2048) {
        // ---- W1t[m, n]: m hidden (16,16,16), n embed (8,16,8) ----
        for (int i = threadIdx.x; i < 2048; i += blockDim.x) {
            int r2 = i >> 7, n3 = (i >> 4) & 7, m3 = i & 15;   // c12:[r2][n3][m3]
            s[(r2 * 16 + m3) * 8 + n3] = c12[i];
        }
        __syncthreads();
        int idx = bid * 256 + threadIdx.x;    // 524288
        int nq = idx & 127;
        int m  = idx >> 7;
        int n1 = nq >> 4, n2 = nq & 15;
        int m1 = m >> 8, m2 = (m >> 4) & 15, m3 = m & 15;
        const float4* p4 = (const float4*)(g_P[0] +
            (((n1 * 16 + m1) * 256) + (n2 * 16 + m2)) * 16);
        float pv[16];
        *(float4*)&pv[0]  = p4[0]; *(float4*)&pv[4]  = p4[1];
        *(float4*)&pv[8]  = p4[2]; *(float4*)&pv[12] = p4[3];
        float acc[8] = {0, 0, 0, 0, 0, 0, 0, 0};
#pragma unroll
        for (int r2 = 0; r2 < 16; ++r2) {
            const float* sr = s + (r2 * 16 + m3) * 8;
#pragma unroll
            for (int j = 0; j < 8; ++j) acc[j] += pv[r2] * sr[j];
        }
        uint4 o;
        o.x = pack2(acc[0], acc[1]); o.y = pack2(acc[2], acc[3]);
        o.z = pack2(acc[4], acc[5]); o.w = pack2(acc[6], acc[7]);
        *(uint4*)(g_W1t + (size_t)m * 1024 + nq * 8) = o;
    } else {
        // ---- W2t[m, n]: m embed (8,16,8), n hidden (16,16,16) ----
        for (int i = threadIdx.x; i < 2048; i += blockDim.x) {
            int r2 = i >> 7, n3 = (i >> 3) & 15, m3 = i & 7;   // c22:[r2][n3][m3]
            s[(r2 * 8 + m3) * 16 + n3] = c22[i];
        }
        __syncthreads();
        int idx = (bid - 2048) * 256 + threadIdx.x;   // 524288
        int nh = idx & 511;
        int m  = idx >> 9;
        int n1 = nh >> 5, n2 = (nh >> 1) & 15, n3b = (nh & 1) * 8;
        int m1 = m >> 7, m2 = (m >> 3) & 15, m3 = m & 7;
        const float4* p4 = (const float4*)(g_P[1] +
            (((n1 * 8 + m1) * 256) + (n2 * 16 + m2)) * 16);
        float pv[16];
        *(float4*)&pv[0]  = p4[0]; *(float4*)&pv[4]  = p4[1];
        *(float4*)&pv[8]  = p4[2]; *(float4*)&pv[12] = p4[3];
        float acc[8] = {0, 0, 0, 0, 0, 0, 0, 0};
#pragma unroll
        for (int r2 = 0; r2 < 16; ++r2) {
            const float* sr = s + (r2 * 8 + m3) * 16 + n3b;
#pragma unroll
            for (int j = 0; j < 8; ++j) acc[j] += pv[r2] * sr[j];
        }
        uint4 o;
        o.x = pack2(acc[0], acc[1]); o.y = pack2(acc[2], acc[3]);
        o.z = pack2(acc[4], acc[5]); o.w = pack2(acc[6], acc[7]);
        *(uint4*)(g_W2t + (size_t)m * 4096 + nh * 8) = o;
    }
}

// ------------------------------- fp16 GEMM --------------------------------
// C[M,N] = A[M,K] * B[N,K]^T + bias.  FUSE=1: C(half)=GELU(.), else C float.
// 512 threads, 16 warps (4m x 4n of 32x32), CTA 128x128, BK=64, 3 stages.
#define STAGE_B 32768

template <int FUSE>
__global__ void __launch_bounds__(512, 2) gemm_f16(
    const __half* __restrict__ A, const __half* __restrict__ B,
    const float* __restrict__ bias, void* __restrict__ Cv,
    int K, int N) {
    extern __shared__ char smem[];
    uint32_t sb = smem_u32(smem);

    int tid  = threadIdx.x;
    int lane = tid & 31;
    int q    = lane & 3;
    int g8   = lane >> 2;
    int warp = tid >> 5;          // 0..15
    int wm   = (warp & 3) * 32;
    int wn   = (warp >> 2) * 32;

    size_t rowBase = (size_t)blockIdx.y * 128;
    size_t colBase = (size_t)blockIdx.x * 128;

    // ---- cp.async geometry: r = tid>>3 + 64*i (i=0,1), j = tid&7 ----------
    int r0 = tid >> 3, j0 = tid & 7;
    uint32_t stOff = (uint32_t)(r0 * 128 + ((j0 ^ (r0 & 7)) << 4)); // +8192*i
    const __half* Asrc = A + (rowBase + r0) * (size_t)K + j0 * 8;
    const __half* Bsrc = B + (colBase + r0) * (size_t)K + j0 * 8;
    size_t strideR = (size_t)64 * K;   // 64-row step between the two chunks

#define LOAD_STAGE(buf) do {                                                 \
    uint32_t stg_ = sb + (uint32_t)(buf) * STAGE_B;                          \
    _Pragma("unroll")                                                        \
    for (int i = 0; i < 2; ++i) {                                            \
        cp16(stg_ + stOff + (uint32_t)(i * 8192),         Asrc + i * strideR); \
        cp16(stg_ + 16384 + stOff + (uint32_t)(i * 8192), Bsrc + i * strideR); \
    }                                                                        \
    CP_COMMIT();                                                             \
    Asrc += 64; Bsrc += 64;                                                  \
} while (0)

    // ---- ldmatrix geometry ----
    int rT  = lane & 15;
    int cT  = lane >> 4;
    int swz = lane & 7;
    uint32_t aB0 = (uint32_t)((wm + rT) * 128);            // + mt*2048
    uint32_t bB0 = (uint32_t)(16384 + (wn + rT) * 128);    // + p*2048
    uint32_t xo[4];
#pragma unroll
    for (int ks = 0; ks < 4; ++ks)
        xo[ks] = ((((uint32_t)(ks * 2) + (uint32_t)cT) ^ (uint32_t)swz) << 4);

    float acc[2][4][4];
#pragma unroll
    for (int i = 0; i < 2; ++i)
#pragma unroll
        for (int j = 0; j < 4; ++j)
#pragma unroll
            for (int k = 0; k < 4; ++k) acc[i][j][k] = 0.f;

    int nS = K >> 6;
    LOAD_STAGE(0);
    LOAD_STAGE(1);

    int buf = 0;
    for (int s = 0; s < nS; ++s) {
        if (s + 2 < nS) CP_WAIT(1); else CP_WAIT(0);
        __syncthreads();
        if (s + 2 < nS) {
            int nb = buf - 1; if (nb < 0) nb += 3;    // (s+2)%3
            LOAD_STAGE(nb);
        }

        uint32_t stg = sb + (uint32_t)buf * STAGE_B;
#pragma unroll
        for (int ks = 0; ks < 4; ++ks) {
            uint32_t af[2][4], bf[4][2];
#pragma unroll
            for (int mt = 0; mt < 2; ++mt)
                ldsm4(af[mt][0], af[mt][1], af[mt][2], af[mt][3],
                      stg + aB0 + (uint32_t)(mt * 2048) + xo[ks]);
#pragma unroll
            for (int p = 0; p < 2; ++p) {
                uint32_t t0, t1, t2, t3;
                ldsm4(t0, t1, t2, t3, stg + bB0 + (uint32_t)(p * 2048) + xo[ks]);
                bf[2 * p][0] = t0;     bf[2 * p][1] = t2;
                bf[2 * p + 1][0] = t1; bf[2 * p + 1][1] = t3;
            }
#pragma unroll
            for (int mt = 0; mt < 2; ++mt)
#pragma unroll
                for (int nt = 0; nt < 4; ++nt)
                    mma_f16(acc[mt][nt], af[mt], bf[nt]);
        }
        buf = (buf == 2) ? 0 : buf + 1;
    }

    // ---- epilogue ----
#pragma unroll
    for (int nt = 0; nt < 4; ++nt) {
        int col = (int)colBase + wn + nt * 8 + 2 * q;
        float bx = bias[col], by = bias[col + 1];
#pragma unroll
        for (int mt = 0; mt < 2; ++mt) {
            size_t row0 = rowBase + wm + mt * 16 + g8;
            float v0 = acc[mt][nt][0] + bx;
            float v1 = acc[mt][nt][1] + by;
            float v2 = acc[mt][nt][2] + bx;
            float v3 = acc[mt][nt][3] + by;
            if (FUSE) {
                v0 = 0.5f * v0 * (1.0f + erff(v0 * 0.70710678118654752f));
                v1 = 0.5f * v1 * (1.0f + erff(v1 * 0.70710678118654752f));
                v2 = 0.5f * v2 * (1.0f + erff(v2 * 0.70710678118654752f));
                v3 = 0.5f * v3 * (1.0f + erff(v3 * 0.70710678118654752f));
                __half* C = (__half*)Cv;
                *(uint32_t*)&C[row0 * (size_t)N + col]       = pack2(v0, v1);
                *(uint32_t*)&C[(row0 + 8) * (size_t)N + col] = pack2(v2, v3);
            } else {
                float* C = (float*)Cv;
                *(float2*)&C[row0 * (size_t)N + col]       = make_float2(v0, v1);
                *(float2*)&C[(row0 + 8) * (size_t)N + col] = make_float2(v2, v3);
            }
        }
    }
#undef LOAD_STAGE
}

// --------------------------------- launch ---------------------------------
extern "C" void kernel_launch(void* const* d_in, const int* in_sizes, int n_in,
                              void* d_out, int out_size) {
    const float* x   = (const float*)d_in[0];
    const float* c10 = (const float*)d_in[1];
    const float* c11 = (const float*)d_in[2];
    const float* c12 = (const float*)d_in[3];
    const float* b1  = (const float*)d_in[4];
    const float* c20 = (const float*)d_in[5];
    const float* c21 = (const float*)d_in[6];
    const float* c22 = (const float*)d_in[7];
    const float* b2  = (const float*)d_in[8];
    float* out = (float*)d_out;

    __half *pW1t, *pW2t, *pH, *pXh;
    cudaGetSymbolAddress((void**)&pW1t, g_W1t);
    cudaGetSymbolAddress((void**)&pW2t, g_W2t);
    cudaGetSymbolAddress((void**)&pH,   g_H);
    cudaGetSymbolAddress((void**)&pXh,  g_Xh);

    const int SMEM = 3 * STAGE_B;   // 98304
    cudaFuncSetAttribute(gemm_f16<1>, cudaFuncAttributeMaxDynamicSharedMemorySize,
                         SMEM);
    cudaFuncSetAttribute(gemm_f16<0>, cudaFuncAttributeMaxDynamicSharedMemorySize,
                         SMEM);

    prep_kernel<<<3072, 256>>>(x, (uint4*)pXh, c10, c11, c20, c21);
    weights_kernel<<<4096, 256>>>(c12, c22);

    // GEMM1: H = half(GELU(Xh @ W1t^T + b1))   grid 32x32
    gemm_f16<1><<<dim3(32, 32), 512, SMEM>>>(pXh, pW1t, b1, pH, 1024, 4096);
    // GEMM2: out = H @ W2t^T + b2              grid 8x32
    gemm_f16<0><<<dim3(8, 32), 512, SMEM>>>(pH, pW2t, b2, out, 4096, 1024);
}